// round 9
// baseline (speedup 1.0000x reference)
#include <cuda_runtime.h>
#include <cuda_bf16.h>

#define RDIM     256
#define NPIX     32768            // 8*64*64
#define THREADS  512

__device__ __forceinline__ float ex2f_(float x){ float r; asm("ex2.approx.ftz.f32 %0,%1;":"=f"(r):"f"(x)); return r; }
__device__ __forceinline__ float lg2f_(float x){ float r; asm("lg2.approx.ftz.f32 %0,%1;":"=f"(r):"f"(x)); return r; }
__device__ __forceinline__ float rcpf_(float x){ float r; asm("rcp.approx.ftz.f32 %0,%1;":"=f"(r):"f"(x)); return r; }

// fast softplus: max(x,0) + ln2 * log2(1 + 2^(-|x|*log2e)); abs err ~1e-7
__device__ __forceinline__ float spf(float x){
    const float L2E = 1.4426950408889634f, LN2 = 0.6931471805599453f;
    return fmaxf(x, 0.f) + LN2 * lg2f_(1.f + ex2f_(-fabsf(x) * L2E));
}

__global__ void __launch_bounds__(THREADS, 3)
mvnd_kernel(const float* __restrict__ rep,
            const float* __restrict__ mW, const float* __restrict__ mb,
            const float* __restrict__ sW, const float* __restrict__ sb,
            float* __restrict__ out)
{
    __shared__ float sraw[9];
    __shared__ float scst[11];
    __shared__ float smax[16];
    __shared__ float ssum[16];

    const int tid  = threadIdx.x;
    const int lane = tid & 31;
    const int w    = tid >> 5;
    const int n    = blockIdx.x;

    // ---------------- Phase 0: 9x256 GEMV (3 mean rows + 6 scale rows) ----------------
    if (w < 9) {
        const float* rp = rep + (size_t)n * RDIM + lane;
        const float* wp = ((w < 3) ? (mW + w * RDIM) : (sW + (w - 3) * RDIM)) + lane;
        float acc = 0.f;
        #pragma unroll
        for (int j = 0; j < 8; j++) acc = fmaf(rp[32 * j], wp[32 * j], acc);
        #pragma unroll
        for (int o = 16; o; o >>= 1) acc += __shfl_xor_sync(0xffffffffu, acc, o);
        if (lane == 0) sraw[w] = acc;
    }
    __syncthreads();

    // ---------------- Phase 1: derived constants (warp 0, all lanes redundant) ----------------
    const float S = 0.84932184f;     // sqrt(0.5*log2(e)):  exp(-0.5 u^2) = ex2(-(S u)^2)
    if (w == 0) {
        const float mx = sraw[0] + mb[0];
        const float my = sraw[1] + mb[1];
        const float mz = sraw[2] + mb[2];
        const float s0 = spf(sraw[3] + sb[0]) + 1e-6f;
        const float s1 = spf(sraw[4] + sb[1]) + 1e-6f;
        const float s2 = spf(sraw[5] + sb[2]) + 1e-6f;
        const float s3 = spf(sraw[6] + sb[3]) + 1e-6f;
        const float s4 = spf(sraw[7] + sb[4]) + 1e-6f;
        const float s5 = spf(sraw[8] + sb[5]) + 1e-6f;
        const float L00 = spf(s0);
        const float L11 = spf(s2);
        const float L22 = spf(s5);
        const float i22 = rcpf_(L22);
        if (lane == 0) {
            scst[0]  = mx;
            scst[1]  = my;
            scst[2]  = mz;
            scst[3]  = rcpf_(L00);     // i00
            scst[4]  = rcpf_(L11);     // i11
            scst[5]  = i22;
            scst[6]  = s1;             // L10
            scst[7]  = s3;             // L20
            scst[8]  = s4 * i22;       // t21 = L21/L22
            scst[9]  = i22 * S;        // i22h
            scst[10] = rcpf_(i22 * S); // 1/i22h
        }
    }
    __syncthreads();

    const float mx   = scst[0], my  = scst[1], mz = scst[2];
    const float i00  = scst[3], i11 = scst[4], i22 = scst[5];
    const float L10  = scst[6], L20 = scst[7], t21 = scst[8];
    const float i22h = scst[9], ri22h = scst[10];

    // ---------------- Phase 2: per-thread 4x x 2y tile constants + peak exponent ----------------
    // element mapping (float4 units, 8192 per row):
    //   vv = z*1024 + y*16 + x4,  x4 = tid&15 (4 x-values), y = 2*(tid>>4)+yi, z = 0..7
    const float yb = 2.f * (float)(tid >> 4) - 31.5f;   // y for yi=0

    float t01[4][2], cxy[4][2];
    float Emax = -1e30f;
    #pragma unroll
    for (int j = 0; j < 4; j++) {
        const float xf   = (float)(4 * (tid & 15) + j) - 31.5f;
        const float y0   = (xf - mx) * i00;
        const float y0h  = y0 * S;
        const float y0h2 = y0h * y0h;
        const float d1   = (my + L10 * y0) * i11;   // y1 = yf*i11 - d1
        const float e2   = (mz + L20 * y0) * i22;   // y2 = zf*i22 - e2 - t21*y1
        #pragma unroll
        for (int yi = 0; yi < 2; yi++) {
            const float yf  = yb + (float)yi;
            const float y1  = fmaf(yf, i11, -d1);
            const float y1h = y1 * S;
            const float t   = -fmaf(y1h, y1h, y0h2);
            const float c   = -S * fmaf(t21, y1, e2);   // y2h(z) = zf*i22h + c
            t01[j][yi] = t;
            cxy[j][yi] = c;
            // nearest grid z to the root of y2h
            float kf = rintf(fmaf(c, -ri22h, 3.5f));
            kf = fminf(fmaxf(kf, 0.f), 7.f);
            const float y2m = fmaf(kf - 3.5f, i22h, c);
            Emax = fmaxf(Emax, fmaf(-y2m, y2m, t));
        }
    }

    // ---------------- Phase 3: block max of peak exponents ----------------
    float em = Emax;
    #pragma unroll
    for (int o = 16; o; o >>= 1) em = fmaxf(em, __shfl_xor_sync(0xffffffffu, em, o));
    if (lane == 0) smax[w] = em;
    __syncthreads();

    float bmax = -1e30f;
    #pragma unroll
    for (int i = 0; i < 16; i++) bmax = fmaxf(bmax, smax[i]);
    const bool live = (Emax >= bmax - 40.f);

    // ---------------- Phase 4: row sum (survivors only), max-shifted ----------------
    float sum = 0.f;
    if (live) {
        #pragma unroll
        for (int j = 0; j < 4; j++) {
            #pragma unroll
            for (int yi = 0; yi < 2; yi++) {
                const float t = t01[j][yi] - bmax;      // shift by row max (ref semantics)
                const float c = cxy[j][yi];
                #pragma unroll
                for (int z = 0; z < 8; z++) {
                    const float zf  = (float)z - 3.5f;
                    const float y2h = fmaf(zf, i22h, c);
                    sum += ex2f_(fmaf(-y2h, y2h, t));
                }
            }
        }
    }
    #pragma unroll
    for (int o = 16; o; o >>= 1) sum += __shfl_xor_sync(0xffffffffu, sum, o);
    if (lane == 0) ssum[w] = sum;
    __syncthreads();

    float tot = 0.f;
    #pragma unroll
    for (int i = 0; i < 16; i++) tot += ssum[i];
    const float li = -lg2f_(tot) - bmax;   // final exponent offset: E + li

    // ---------------- Phase 5: store (zeros fast-path / recompute normalized) ----------------
    float4* out4 = (float4*)(out + (size_t)n * NPIX);
    const int base = ((tid >> 4) << 5) + (tid & 15);

    if (!live) {
        const float4 zz = make_float4(0.f, 0.f, 0.f, 0.f);
        #pragma unroll
        for (int z = 0; z < 8; z++) {
            __stcs(&out4[base + z * 1024],      zz);
            __stcs(&out4[base + z * 1024 + 16], zz);
        }
    } else {
        #pragma unroll
        for (int j = 0; j < 4; j++) {
            #pragma unroll
            for (int yi = 0; yi < 2; yi++) t01[j][yi] += li;
        }
        #pragma unroll
        for (int z = 0; z < 8; z++) {
            const float zf = (float)z - 3.5f;
            #pragma unroll
            for (int yi = 0; yi < 2; yi++) {
                float4 v;
                {
                    const float a = fmaf(zf, i22h, cxy[0][yi]);
                    v.x = ex2f_(fmaf(-a, a, t01[0][yi]));
                }
                {
                    const float a = fmaf(zf, i22h, cxy[1][yi]);
                    v.y = ex2f_(fmaf(-a, a, t01[1][yi]));
                }
                {
                    const float a = fmaf(zf, i22h, cxy[2][yi]);
                    v.z = ex2f_(fmaf(-a, a, t01[2][yi]));
                }
                {
                    const float a = fmaf(zf, i22h, cxy[3][yi]);
                    v.w = ex2f_(fmaf(-a, a, t01[3][yi]));
                }
                __stcs(&out4[base + z * 1024 + yi * 16], v);
            }
        }
    }
}

extern "C" void kernel_launch(void* const* d_in, const int* in_sizes, int n_in,
                              void* d_out, int out_size)
{
    const float* rep = (const float*)d_in[0];   // (1024, 256)
    const float* mW  = (const float*)d_in[1];   // (3, 256)
    const float* mb  = (const float*)d_in[2];   // (3,)
    const float* sW  = (const float*)d_in[3];   // (6, 256)
    const float* sb  = (const float*)d_in[4];   // (6,)
    float* out = (float*)d_out;                 // (1024, 32768)

    mvnd_kernel<<<1024, THREADS>>>(rep, mW, mb, sW, sb, out);
}

// round 10
// speedup vs baseline: 1.0719x; 1.0719x over previous
#include <cuda_runtime.h>
#include <cuda_bf16.h>

#define RDIM     256
#define NPIX     32768            // 8*64*64
#define THREADS  512

__device__ __forceinline__ float ex2f_(float x){ float r; asm("ex2.approx.ftz.f32 %0,%1;":"=f"(r):"f"(x)); return r; }
__device__ __forceinline__ float lg2f_(float x){ float r; asm("lg2.approx.ftz.f32 %0,%1;":"=f"(r):"f"(x)); return r; }
__device__ __forceinline__ float rcpf_(float x){ float r; asm("rcp.approx.ftz.f32 %0,%1;":"=f"(r):"f"(x)); return r; }

// fast softplus: max(x,0) + ln2 * log2(1 + 2^(-|x|*log2e))
__device__ __forceinline__ float spf(float x){
    const float L2E = 1.4426950408889634f, LN2 = 0.6931471805599453f;
    return fmaxf(x, 0.f) + LN2 * lg2f_(1.f + ex2f_(-fabsf(x) * L2E));
}

__global__ void __launch_bounds__(THREADS, 3)
mvnd_kernel(const float* __restrict__ rep,
            const float* __restrict__ mW, const float* __restrict__ mb,
            const float* __restrict__ sW, const float* __restrict__ sb,
            float* __restrict__ out)
{
    __shared__ float sraw[9];
    __shared__ float scst[12];
    __shared__ float smax[16];
    __shared__ float ssum[16];

    const int tid  = threadIdx.x;
    const int lane = tid & 31;
    const int w    = tid >> 5;
    const int n    = blockIdx.x;

    // ---------------- Phase 0: 9x256 GEMV ----------------
    if (w < 9) {
        const float* rp = rep + (size_t)n * RDIM + lane;
        const float* wp = ((w < 3) ? (mW + w * RDIM) : (sW + (w - 3) * RDIM)) + lane;
        float acc = 0.f;
        #pragma unroll
        for (int j = 0; j < 8; j++) acc = fmaf(rp[32 * j], wp[32 * j], acc);
        #pragma unroll
        for (int o = 16; o; o >>= 1) acc += __shfl_xor_sync(0xffffffffu, acc, o);
        if (lane == 0) sraw[w] = acc;
    }
    __syncthreads();

    // ---------------- Phase 1: derived constants (warp 0 redundant) ----------------
    const float S = 0.84932184f;     // sqrt(0.5*log2(e))
    if (w == 0) {
        const float mx = sraw[0] + mb[0];
        const float my = sraw[1] + mb[1];
        const float mz = sraw[2] + mb[2];
        const float s0 = spf(sraw[3] + sb[0]) + 1e-6f;
        const float s1 = spf(sraw[4] + sb[1]) + 1e-6f;
        const float s2 = spf(sraw[5] + sb[2]) + 1e-6f;
        const float s3 = spf(sraw[6] + sb[3]) + 1e-6f;
        const float s4 = spf(sraw[7] + sb[4]) + 1e-6f;
        const float s5 = spf(sraw[8] + sb[5]) + 1e-6f;
        const float L00 = spf(s0);
        const float L11 = spf(s2);
        const float L22 = spf(s5);
        const float i22 = rcpf_(L22);
        const float i22h = i22 * S;
        if (lane == 0) {
            scst[0]  = mx;
            scst[1]  = my;
            scst[2]  = mz;
            scst[3]  = rcpf_(L00);           // i00
            scst[4]  = rcpf_(L11);           // i11
            scst[5]  = i22;
            scst[6]  = s1;                   // L10
            scst[7]  = s3;                   // L20
            scst[8]  = s4 * i22;             // t21
            scst[9]  = i22h;
            scst[10] = rcpf_(i22h);
            scst[11] = ex2f_(-2.f * i22h * i22h);  // G: ratio-of-ratios along z
        }
    }
    __syncthreads();

    const float mx   = scst[0], my  = scst[1], mz = scst[2];
    const float i00  = scst[3], i11 = scst[4], i22 = scst[5];
    const float L10  = scst[6], L20 = scst[7], t21 = scst[8];
    const float i22h = scst[9], ri22h = scst[10], G = scst[11];

    // ---------------- Phase 2: per-thread column constants + peak exponent ----------------
    // element mapping (float4 units): vv = z*1024 + y*16 + x4
    //   x4 = tid&15 (4 x per thread), y = 2*(tid>>4)+yi, z = 0..7
    // per column: arg(z) = t - (zf*i22h + c)^2, zf = z-3.5
    //   a0 = arg(0);  d0 = arg(1)-arg(0) = -2*i22h*y2h(0) - i22h^2
    const float yb = 2.f * (float)(tid >> 4) - 31.5f;

    float a0[4][2], d0[4][2];
    float Emax = -1e30f;
    #pragma unroll
    for (int j = 0; j < 4; j++) {
        const float xf   = (float)(4 * (tid & 15) + j) - 31.5f;
        const float y0   = (xf - mx) * i00;
        const float y0h  = y0 * S;
        const float y0h2 = y0h * y0h;
        const float d1   = (my + L10 * y0) * i11;
        const float e2   = (mz + L20 * y0) * i22;
        #pragma unroll
        for (int yi = 0; yi < 2; yi++) {
            const float yf  = yb + (float)yi;
            const float y1  = fmaf(yf, i11, -d1);
            const float y1h = y1 * S;
            const float t   = -fmaf(y1h, y1h, y0h2);
            const float c   = -S * fmaf(t21, y1, e2);    // y2h(z) = zf*i22h + c
            const float y20 = fmaf(-3.5f, i22h, c);      // y2h at z=0
            a0[j][yi] = fmaf(-y20, y20, t);
            d0[j][yi] = fmaf(-2.f * i22h, y20, -i22h * i22h);
            // peak over valid z (clamped root)
            float kf = rintf(fmaf(c, -ri22h, 3.5f));
            kf = fminf(fmaxf(kf, 0.f), 7.f);
            const float y2m = fmaf(kf - 3.5f, i22h, c);
            Emax = fmaxf(Emax, fmaf(-y2m, y2m, t));
        }
    }

    // ---------------- Phase 3: block max of peak exponents ----------------
    float em = Emax;
    #pragma unroll
    for (int o = 16; o; o >>= 1) em = fmaxf(em, __shfl_xor_sync(0xffffffffu, em, o));
    if (lane == 0) smax[w] = em;
    __syncthreads();

    float bmax = -1e30f;
    #pragma unroll
    for (int i = 0; i < 16; i++) bmax = fmaxf(bmax, smax[i]);
    const bool live = (Emax >= bmax - 40.f);

    float4* out4 = (float4*)(out + (size_t)n * NPIX);
    const int base = ((tid >> 4) << 5) + (tid & 15);

    // ---------------- Phase 4a: dead threads store zeros NOW (overlaps live sums) ----------------
    if (!live) {
        const float4 zz = make_float4(0.f, 0.f, 0.f, 0.f);
        #pragma unroll
        for (int z = 0; z < 8; z++) {
            __stcs(&out4[base + z * 1024],      zz);
            __stcs(&out4[base + z * 1024 + 16], zz);
        }
    }

    // ---------------- Phase 4b: row sum via geometric recurrence ----------------
    float sum = 0.f;
    if (live) {
        #pragma unroll
        for (int j = 0; j < 4; j++) {
            #pragma unroll
            for (int yi = 0; yi < 2; yi++) {
                float v = ex2f_(a0[j][yi] - bmax);   // arg <= 0 after shift
                float r = ex2f_(d0[j][yi]);
                sum += v;
                #pragma unroll
                for (int z = 1; z < 8; z++) {
                    v *= r;
                    r *= G;
                    sum += v;
                }
            }
        }
    }
    #pragma unroll
    for (int o = 16; o; o >>= 1) sum += __shfl_xor_sync(0xffffffffu, sum, o);
    if (lane == 0) ssum[w] = sum;
    __syncthreads();

    // ---------------- Phase 5: live threads store normalized values ----------------
    if (live) {
        float tot = 0.f;
        #pragma unroll
        for (int i = 0; i < 16; i++) tot += ssum[i];
        const float li = -lg2f_(tot) - bmax;   // fold 1/sum + max-shift into exponent

        #pragma unroll
        for (int yi = 0; yi < 2; yi++) {
            float v[4], r[4];
            #pragma unroll
            for (int j = 0; j < 4; j++) {
                v[j] = ex2f_(a0[j][yi] + li);
                r[j] = ex2f_(d0[j][yi]);
            }
            #pragma unroll
            for (int z = 0; z < 8; z++) {
                __stcs(&out4[base + z * 1024 + yi * 16],
                       make_float4(v[0], v[1], v[2], v[3]));
                if (z < 7) {
                    #pragma unroll
                    for (int j = 0; j < 4; j++) { v[j] *= r[j]; r[j] *= G; }
                }
            }
        }
    }
}

extern "C" void kernel_launch(void* const* d_in, const int* in_sizes, int n_in,
                              void* d_out, int out_size)
{
    const float* rep = (const float*)d_in[0];   // (1024, 256)
    const float* mW  = (const float*)d_in[1];   // (3, 256)
    const float* mb  = (const float*)d_in[2];   // (3,)
    const float* sW  = (const float*)d_in[3];   // (6, 256)
    const float* sb  = (const float*)d_in[4];   // (6,)
    float* out = (float*)d_out;                 // (1024, 32768)

    mvnd_kernel<<<1024, THREADS>>>(rep, mW, mb, sW, sb, out);
}